// round 5
// baseline (speedup 1.0000x reference)
#include <cuda_runtime.h>
#include <cuda_bf16.h>
#include <math.h>
#include <stdint.h>

#define Bn 16384
#define Dn 512
#define Kn 2048

// ======================= PTX helpers (baseline compute_103-safe) =======================
__device__ __forceinline__ uint32_t smem_to_u32(const void* p){
    uint32_t a;
    asm("{ .reg .u64 t; cvta.to.shared.u64 t, %1; cvt.u32.u64 %0, t; }" : "=r"(a) : "l"(p));
    return a;
}
#define CP_ASYNC16(dst, src) \
    asm volatile("cp.async.cg.shared.global [%0], [%1], 16;" :: "r"(dst), "l"(src) : "memory")
#define CP_COMMIT() asm volatile("cp.async.commit_group;" ::: "memory")
#define CP_WAIT(n)  asm volatile("cp.async.wait_group %0;" :: "n"(n) : "memory")
#define LDMATRIX_X4(r0,r1,r2,r3,addr) \
    asm volatile("ldmatrix.sync.aligned.m8n8.x4.shared.b16 {%0,%1,%2,%3}, [%4];" \
        : "=r"(r0),"=r"(r1),"=r"(r2),"=r"(r3) : "r"(addr))

__device__ __forceinline__ void mma16816(float* c, const uint32_t* a, const uint32_t* b){
    asm volatile("mma.sync.aligned.m16n8k16.row.col.f32.bf16.bf16.f32 "
        "{%0,%1,%2,%3}, {%4,%5,%6,%7}, {%8,%9}, {%0,%1,%2,%3};"
        : "+f"(c[0]),"+f"(c[1]),"+f"(c[2]),"+f"(c[3])
        : "r"(a[0]),"r"(a[1]),"r"(a[2]),"r"(a[3]), "r"(b[0]),"r"(b[1]));
}

// ======================= workspaces =======================
__device__ float g_L1[33554432];   // [B,K] logits view 1
__device__ float g_L2[33554432];
__device__ __nv_bfloat16 g_znh1[8388608], g_znl1[8388608];   // zn hi/lo [B,D]
__device__ __nv_bfloat16 g_znh2[8388608], g_znl2[8388608];
__device__ __nv_bfloat16 g_zth1[8388608], g_ztl1[8388608];   // z^T hi/lo [D,B]
__device__ __nv_bfloat16 g_zth2[8388608], g_ztl2[8388608];
__device__ __nv_bfloat16 g_wh[1048576], g_wl[1048576];       // W hi/lo [K,D]
__device__ float g_G1[262144], g_G2[262144];
__device__ float g_csum[2][512];
__device__ float g_t[2][3][2048];           // sinkhorn col sums, per iter
__device__ float g_u1[2048], g_u2[2048], g_lu1[2048], g_lu2[2048];
__device__ float g_v1[16384], g_v2[16384];
__device__ float g_lse1[16384], g_lse2[16384];
__device__ int   g_am1[16384], g_am2[16384];
__device__ double g_S[2];
__device__ double g_ce[2];
__device__ float g_avgp[2048];
__device__ int   g_hist[2048];
__device__ int   g_accc[2];
__device__ float g_misc[4];

__device__ __forceinline__ float* LB(int v){ return v ? g_L2 : g_L1; }
__device__ __forceinline__ float* UB(int v){ return v ? g_u2 : g_u1; }
__device__ __forceinline__ float* VBv(int v){ return v ? g_v2 : g_v1; }
__device__ __forceinline__ float* LSEB(int v){ return v ? g_lse2 : g_lse1; }
__device__ __forceinline__ int*   AMB(int v){ return v ? g_am2 : g_am1; }
__device__ __forceinline__ float* GBv(int v){ return v ? g_G2 : g_G1; }

__device__ __forceinline__ void bsplit(float x, __nv_bfloat16& h, __nv_bfloat16& l){
    h = __float2bfloat16(x);
    l = __float2bfloat16(x - __bfloat162float(h));
}

// ======================= zeroing (every launch — keeps replays idempotent) ===========
// 1024 blocks x 256 threads = 262144 threads: covers G (and small arrays on low ids)
__global__ void k_zero_main(){
    int i = blockIdx.x*256 + threadIdx.x;
    g_G1[i]=0.f; g_G2[i]=0.f;                                  // atomic split-K target
    if (i < 2048){ g_avgp[i]=0.f; g_hist[i]=0; }
    if (i < 1024){ ((float*)g_csum)[i]=0.f; }
    if (i < 12288){ ((float*)g_t)[i]=0.f; }
    if (i == 0){
        g_S[0]=0.0; g_S[1]=0.0; g_ce[0]=0.0; g_ce[1]=0.0;
        g_accc[0]=0; g_accc[1]=0;
        g_misc[0]=0.f; g_misc[1]=0.f; g_misc[2]=0.f; g_misc[3]=0.f;
    }
}

// ======================= row l2 normalize -> bf16 hi/lo =======================
__global__ void k_rownorm(const float* __restrict__ z, int view){
    int row = blockIdx.x, t = threadIdx.x;
    __shared__ float sm[128];
    float4 v = reinterpret_cast<const float4*>(z)[(size_t)row*128 + t];
    float s = v.x*v.x + v.y*v.y + v.z*v.z + v.w*v.w;
    sm[t]=s; __syncthreads();
    for (int o=64;o;o>>=1){ if (t<o) sm[t]+=sm[t+o]; __syncthreads(); }
    float inv = 1.f / fmaxf(sqrtf(sm[0]), 1e-12f);
    __nv_bfloat16* H = view ? g_znh2 : g_znh1;
    __nv_bfloat16* L = view ? g_znl2 : g_znl1;
    size_t o = (size_t)row*512 + t*4;
    __nv_bfloat16 h0,h1,h2,h3,l0,l1,l2,l3;
    bsplit(v.x*inv,h0,l0); bsplit(v.y*inv,h1,l1);
    bsplit(v.z*inv,h2,l2); bsplit(v.w*inv,h3,l3);
    __nv_bfloat162* Hp = reinterpret_cast<__nv_bfloat162*>(H + o);
    __nv_bfloat162* Lp = reinterpret_cast<__nv_bfloat162*>(L + o);
    Hp[0] = __nv_bfloat162(h0,h1); Hp[1] = __nv_bfloat162(h2,h3);
    Lp[0] = __nv_bfloat162(l0,l1); Lp[1] = __nv_bfloat162(l2,l3);
}

// ======================= transpose z -> zT bf16 hi/lo, + column sums =======================
__global__ void k_ztrans(const float* __restrict__ z, int view){
    __shared__ float t[32][33];
    __shared__ float cs[8][32];
    __nv_bfloat16* TH = view ? g_zth2 : g_zth1;
    __nv_bfloat16* TL = view ? g_ztl2 : g_ztl1;
    int x0 = blockIdx.x*32, y0 = blockIdx.y*32;
    int tx = threadIdx.x, ty = threadIdx.y;
    #pragma unroll
    for (int i=0;i<32;i+=8)
        t[ty+i][tx] = z[(size_t)(y0+ty+i)*512 + x0 + tx];
    __syncthreads();
    cs[ty][tx] = t[ty][tx] + t[ty+8][tx] + t[ty+16][tx] + t[ty+24][tx];
    #pragma unroll
    for (int i=0;i<32;i+=8){
        float v = t[tx][ty+i];
        __nv_bfloat16 h,l; bsplit(v,h,l);
        size_t o = (size_t)(x0+ty+i)*16384 + y0 + tx;
        TH[o]=h; TL[o]=l;
    }
    __syncthreads();
    if (ty==0){
        float s = cs[0][tx]+cs[1][tx]+cs[2][tx]+cs[3][tx]
                + cs[4][tx]+cs[5][tx]+cs[6][tx]+cs[7][tx];
        atomicAdd(&g_csum[view][x0+tx], s);
    }
}

// ======================= W -> bf16 hi/lo =======================
__global__ void k_wsplit(const float* __restrict__ W){
    int i = blockIdx.x*512 + threadIdx.x;
    bsplit(W[i], g_wh[i], g_wl[i]);
}

// ======================= HMMA GEMM: BM=128, BN=256, BK=32, 3-stage, 3-term split ==========
#define TBM 128
#define TBN 256
#define ROWB 80
#define STG_A (TBM*ROWB)             // 10240
#define STG_SZ (TBM*ROWB + TBN*ROWB) // 30720
#define G_SMEM (3*STG_SZ)            // 92160

__global__ void __launch_bounds__(256,1) k_mma_gemm(int which){
    const __nv_bfloat16 *Ah,*Al,*Bh,*Bl;
    float* C; size_t ldk; int ldc, atomic_epi;
    if (which == 0){ Ah=g_znh1; Al=g_znl1; Bh=g_wh; Bl=g_wl; C=g_L1; ldk=512; ldc=2048; atomic_epi=0; }
    else if (which == 1){ Ah=g_znh2; Al=g_znl2; Bh=g_wh; Bl=g_wl; C=g_L2; ldk=512; ldc=2048; atomic_epi=0; }
    else if (which == 2){ Ah=g_zth1; Al=g_ztl1; Bh=g_zth1; Bl=g_ztl1; C=g_G1; ldk=16384; ldc=512; atomic_epi=1; }
    else { Ah=g_zth2; Al=g_ztl2; Bh=g_zth2; Bl=g_ztl2; C=g_G2; ldk=16384; ldc=512; atomic_epi=1; }

    extern __shared__ __align__(128) char smem[];
    uint32_t sb = smem_to_u32(smem);

    int tid = threadIdx.x;
    int wid = tid >> 5, lane = tid & 31;
    int wm = wid >> 2, wn = wid & 3;        // warp tile 64x64
    int g = lane >> 2, tig = lane & 3;

    int bm = blockIdx.y*TBM, bn = blockIdx.x*TBN;
    size_t kz = (size_t)blockIdx.z * 512;

    const __nv_bfloat16* Aterm[3] = {Ah, Ah, Al};
    const __nv_bfloat16* Bterm[3] = {Bh, Bl, Bh};

    float acc[4][8][4];
    #pragma unroll
    for (int mf=0;mf<4;mf++)
        #pragma unroll
        for (int nf=0;nf<8;nf++)
            #pragma unroll
            for (int q=0;q<4;q++) acc[mf][nf][q]=0.f;

    int ra = tid >> 2, ca = tid & 3;

    auto load_stage = [&](int it, int s){
        int term = it >> 4; int kb = it & 15;
        const __nv_bfloat16* Ap = Aterm[term] + (size_t)bm*ldk + kz + kb*32;
        const __nv_bfloat16* Bp = Bterm[term] + (size_t)bn*ldk + kz + kb*32;
        uint32_t baseA = sb + s*STG_SZ;
        uint32_t baseB = baseA + STG_A;
        #pragma unroll
        for (int j=0;j<2;j++){
            int r = ra + j*64;
            CP_ASYNC16(baseA + r*ROWB + ca*16, Ap + (size_t)r*ldk + ca*8);
        }
        #pragma unroll
        for (int j=0;j<4;j++){
            int r = ra + j*64;
            CP_ASYNC16(baseB + r*ROWB + ca*16, Bp + (size_t)r*ldk + ca*8);
        }
        CP_COMMIT();
    };

    load_stage(0,0);
    load_stage(1,1);

    int arow_base = wm*64 + (lane&7) + ((lane>>3)&1)*8;
    int akoff     = (lane>>4)*16;
    int brow_base = wn*64 + (lane&7) + (lane>>4)*8;
    int bkoff     = ((lane>>3)&1)*16;

    const int KITER = 48;
    for (int it=0; it<KITER; it++){
        int s = it - (it/3)*3;
        if (it+1 < KITER) { CP_WAIT(1); } else { CP_WAIT(0); }
        __syncthreads();
        if (it+2 < KITER){ int s2 = (it+2) - ((it+2)/3)*3; load_stage(it+2, s2); }
        uint32_t baseA = sb + s*STG_SZ;
        uint32_t baseB = baseA + STG_A;
        #pragma unroll
        for (int ks=0; ks<2; ks++){
            uint32_t a[4][4], b[8][2];
            #pragma unroll
            for (int mf=0; mf<4; mf++){
                uint32_t ad = baseA + (arow_base + mf*16)*ROWB + ks*32 + akoff;
                LDMATRIX_X4(a[mf][0],a[mf][1],a[mf][2],a[mf][3], ad);
            }
            #pragma unroll
            for (int nh=0; nh<4; nh++){
                uint32_t bd = baseB + (brow_base + nh*16)*ROWB + ks*32 + bkoff;
                LDMATRIX_X4(b[nh*2][0],b[nh*2][1],b[nh*2+1][0],b[nh*2+1][1], bd);
            }
            #pragma unroll
            for (int mf=0; mf<4; mf++)
                #pragma unroll
                for (int nf=0; nf<8; nf++)
                    mma16816(acc[mf][nf], a[mf], b[nf]);
        }
    }

    // epilogue
    #pragma unroll
    for (int mf=0; mf<4; mf++){
        int r0 = bm + wm*64 + mf*16 + g;
        #pragma unroll
        for (int nf=0; nf<8; nf++){
            int cc = bn + wn*64 + nf*8 + tig*2;
            if (!atomic_epi){
                float2* p0 = reinterpret_cast<float2*>(C + (size_t)r0*ldc + cc);
                float2* p1 = reinterpret_cast<float2*>(C + (size_t)(r0+8)*ldc + cc);
                *p0 = make_float2(acc[mf][nf][0], acc[mf][nf][1]);
                *p1 = make_float2(acc[mf][nf][2], acc[mf][nf][3]);
            } else {
                atomicAdd(C + (size_t)r0*ldc + cc,       acc[mf][nf][0]);
                atomicAdd(C + (size_t)r0*ldc + cc + 1,   acc[mf][nf][1]);
                atomicAdd(C + (size_t)(r0+8)*ldc + cc,   acc[mf][nf][2]);
                atomicAdd(C + (size_t)(r0+8)*ldc + cc+1, acc[mf][nf][3]);
            }
        }
    }
}

// ======================= covariance / variance losses (both views) =======================
__global__ void k_covfin(){
    int view = blockIdx.y;
    int i = blockIdx.x, j = threadIdx.x;
    __shared__ float sm[512];
    const float* G = GBv(view);
    float mi = g_csum[view][i] * (1.f/16384.f);
    float mj = g_csum[view][j] * (1.f/16384.f);
    float Cij = (G[(size_t)i*512 + j] - 16384.f*mi*mj) * (1.f/16383.f);
    float c2 = (i==j) ? 0.f : Cij*Cij;
    sm[j]=c2; __syncthreads();
    for (int o=256;o;o>>=1){ if (j<o) sm[j]+=sm[j+o]; __syncthreads(); }
    if (j==0) atomicAdd(&g_misc[view*2+1], sm[0]*(1.f/512.f));
    if (j==i){
        float term = fmaxf(0.f, 0.2f - sqrtf(Cij + 1e-8f));
        atomicAdd(&g_misc[view*2+0], term*(1.f/512.f));
    }
}

// ======================= per-row max/argmax + logsumexp =======================
__global__ void k_rowstats(int view){
    int b = blockIdx.x, tid = threadIdx.x;
    const float* L = LB(view);
    const float4* Lr = reinterpret_cast<const float4*>(L + (size_t)b*2048);
    float4 x0 = Lr[tid*2], x1 = Lr[tid*2+1];
    float v[8] = {x0.x,x0.y,x0.z,x0.w,x1.x,x1.y,x1.z,x1.w};
    float m = v[0]; int mi = tid*8;
    #pragma unroll
    for (int j=1;j<8;j++) if (v[j]>m){ m=v[j]; mi=tid*8+j; }
    __shared__ float sm[256]; __shared__ int si[256];
    sm[tid]=m; si[tid]=mi; __syncthreads();
    for (int o=128;o;o>>=1){
        if (tid<o){
            if (sm[tid+o]>sm[tid] || (sm[tid+o]==sm[tid] && si[tid+o]<si[tid])){
                sm[tid]=sm[tid+o]; si[tid]=si[tid+o];
            }
        }
        __syncthreads();
    }
    float M = sm[0]; int gidx = si[0];
    __syncthreads();
    float se=0.f;
    #pragma unroll
    for (int j=0;j<8;j++) se += __expf((v[j]-M)*10.f);
    sm[tid]=se; __syncthreads();
    for (int o=128;o;o>>=1){ if (tid<o) sm[tid]+=sm[tid+o]; __syncthreads(); }
    if (tid==0){ LSEB(view)[b] = M*10.f + logf(sm[0]); AMB(view)[b] = gidx; }
}

// ======================= sinkhorn column pass (writes g_t[view][iter]) =======================
__global__ void k_colpass(int view, int iter){
    __shared__ float sm[256];
    int k = blockIdx.x*256 + threadIdx.x;
    size_t b0 = (size_t)blockIdx.y * 128;
    const float* L = LB(view);
    float s = 0.f;
    if (iter > 0){
        const float* v = VBv(view);
        #pragma unroll 8
        for (int r=0;r<128;r++)
            s += __expf(20.f * L[(b0+r)*2048 + k]) * v[b0+r];
    } else {
        #pragma unroll 8
        for (int r=0;r<128;r++)
            s += __expf(20.f * L[(b0+r)*2048 + k]);
    }
    atomicAdd(&g_t[view][iter][k], s);
    if (iter == 0){
        sm[threadIdx.x]=s; __syncthreads();
        for (int o=128;o;o>>=1){ if (threadIdx.x<o) sm[threadIdx.x]+=sm[threadIdx.x+o]; __syncthreads(); }
        if (threadIdx.x==0) atomicAdd(&g_S[view], (double)sm[0]);
    }
}

// ======================= u update (both views, +logu on last iter) =======================
__global__ void k_u(int iter){
    int idx = blockIdx.x*256 + threadIdx.x;   // 16 blocks -> 4096
    int view = idx >> 11, k = idx & 2047;
    float t = g_t[view][iter][k];
    float u = (iter==0) ? (float)(g_S[view]) / (2048.f * t) : 1.f / (2048.f * t);
    (view ? g_u2 : g_u1)[k] = u;
    if (iter == 2) (view ? g_lu2 : g_lu1)[k] = logf(u);
}

// ======================= sinkhorn row pass =======================
__global__ void k_rowpass(int view){
    int b = blockIdx.x, tid = threadIdx.x;
    const float* L = LB(view);
    const float4* Lr = reinterpret_cast<const float4*>(L + (size_t)b*2048);
    const float4* Ur = reinterpret_cast<const float4*>(UB(view));
    float s = 0.f;
    #pragma unroll
    for (int j=0;j<2;j++){
        float4 x = Lr[tid*2+j]; float4 uu = Ur[tid*2+j];
        s += __expf(20.f*x.x)*uu.x + __expf(20.f*x.y)*uu.y
           + __expf(20.f*x.z)*uu.z + __expf(20.f*x.w)*uu.w;
    }
    __shared__ float sm[256];
    sm[tid]=s; __syncthreads();
    for (int o=128;o;o>>=1){ if (tid<o) sm[tid]+=sm[tid+o]; __syncthreads(); }
    if (tid==0) VBv(view)[b] = 1.f / (16384.f * sm[0]);
}

// ======================= fused final pass: CE, avg_probs, acc, hist =======================
__global__ void k_final(){
    __shared__ float s_avgp[2048];
    __shared__ float smf[256]; __shared__ int smi[256];
    __shared__ double smd[256];
    int tid = threadIdx.x;
    int kbase = tid*8;
    float U1[8],U2[8],LU1[8],LU2[8];
    #pragma unroll
    for (int j=0;j<8;j++){
        U1[j]=g_u1[kbase+j]; U2[j]=g_u2[kbase+j];
        LU1[j]=g_lu1[kbase+j]; LU2[j]=g_lu2[kbase+j];
        s_avgp[kbase+j]=0.f;
    }
    __syncthreads();
    double tce1=0.0, tce2=0.0;
    int tacc1=0, tacc2=0;
    int b0 = blockIdx.x*16;
    for (int r=0;r<16;r++){
        int b = b0 + r;
        const float4* L1r = reinterpret_cast<const float4*>(g_L1 + (size_t)b*2048);
        const float4* L2r = reinterpret_cast<const float4*>(g_L2 + (size_t)b*2048);
        float4 a0=L1r[tid*2], a1=L1r[tid*2+1];
        float4 c0=L2r[tid*2], c1=L2r[tid*2+1];
        float A[8]={a0.x,a0.y,a0.z,a0.w,a1.x,a1.y,a1.z,a1.w};
        float C[8]={c0.x,c0.y,c0.z,c0.w,c1.x,c1.y,c1.z,c1.w};
        float cv1 = 16384.f*g_v1[b], cv2 = 16384.f*g_v2[b];
        float ls1 = g_lse1[b], ls2 = g_lse2[b];
        float sc1=0.f, sc2=0.f;
        float m1=-1e30f, m2=-1e30f; int i1=0, i2=0;
        #pragma unroll
        for (int j=0;j<8;j++){
            float a=A[j], c=C[j];
            float lp1 = 10.f*a - ls1;
            float lp2 = 10.f*c - ls2;
            float t1 = cv1*U1[j]*__expf(20.f*a);
            float t2 = cv2*U2[j]*__expf(20.f*c);
            sc1 += t1*lp2;
            sc2 += t2*lp1;
            s_avgp[kbase+j] += __expf(lp1) + __expf(lp2);
            float g1 = 20.f*a + LU1[j];
            if (g1>m1){ m1=g1; i1=kbase+j; }
            float g2 = 20.f*c + LU2[j];
            if (g2>m2){ m2=g2; i2=kbase+j; }
        }
        tce1 += (double)sc1; tce2 += (double)sc2;
        smf[tid]=m2; smi[tid]=i2; __syncthreads();
        for (int o=128;o;o>>=1){
            if (tid<o && (smf[tid+o]>smf[tid] || (smf[tid+o]==smf[tid] && smi[tid+o]<smi[tid]))){
                smf[tid]=smf[tid+o]; smi[tid]=smi[tid+o];
            }
            __syncthreads();
        }
        if (tid==0 && smi[0]==g_am1[b]) tacc1++;
        __syncthreads();
        smf[tid]=m1; smi[tid]=i1; __syncthreads();
        for (int o=128;o;o>>=1){
            if (tid<o && (smf[tid+o]>smf[tid] || (smf[tid+o]==smf[tid] && smi[tid+o]<smi[tid]))){
                smf[tid]=smf[tid+o]; smi[tid]=smi[tid+o];
            }
            __syncthreads();
        }
        if (tid==0 && smi[0]==g_am2[b]) tacc2++;
        __syncthreads();
    }
    smd[tid]=tce1; __syncthreads();
    for (int o=128;o;o>>=1){ if (tid<o) smd[tid]+=smd[tid+o]; __syncthreads(); }
    if (tid==0) atomicAdd(&g_ce[0], smd[0]);
    __syncthreads();
    smd[tid]=tce2; __syncthreads();
    for (int o=128;o;o>>=1){ if (tid<o) smd[tid]+=smd[tid+o]; __syncthreads(); }
    if (tid==0) atomicAdd(&g_ce[1], smd[0]);
    __syncthreads();
    #pragma unroll
    for (int j=0;j<8;j++) atomicAdd(&g_avgp[kbase+j], s_avgp[kbase+j]);
    if (tid==0){ atomicAdd(&g_accc[0], tacc1); atomicAdd(&g_accc[1], tacc2); }
    if (tid < 16){
        atomicAdd(&g_hist[g_am1[b0+tid]], 1);
        atomicAdd(&g_hist[g_am2[b0+tid]], 1);
    }
}

__global__ void k_finalize(float* __restrict__ out){
    __shared__ double smd[256];
    int tid = threadIdx.x;
    double sh=0.0, sp=0.0;
    for (int j=0;j<8;j++){
        int k = tid*8 + j;
        double hp = (double)g_hist[k] / 32768.0;
        sh += hp * log(hp + 1e-7);
        double pp = (double)g_avgp[k] / 32768.0;
        sp += pp * log(pp + 1e-7);
    }
    smd[tid]=sh; __syncthreads();
    for (int o=128;o;o>>=1){ if (tid<o) smd[tid]+=smd[tid+o]; __syncthreads(); }
    double H = smd[0]; __syncthreads();
    smd[tid]=sp; __syncthreads();
    for (int o=128;o;o>>=1){ if (tid<o) smd[tid]+=smd[tid+o]; __syncthreads(); }
    double P = smd[0];
    if (tid==0){
        double ce = -0.5 * (g_ce[0]/16384.0 + g_ce[1]/16384.0);
        float lvar = g_misc[0] + g_misc[2];
        float lcov = g_misc[1] + g_misc[3];
        double loss = 15.0*ce + (double)lvar + (double)lcov;
        out[0] = (float)loss;
        out[1] = (float)ce;
        out[2] = lvar;
        out[3] = lcov;
        out[4] = (float)exp(-H);
        out[5] = (float)exp(-P);
        out[6] = 0.5f * ((float)g_accc[0] + (float)g_accc[1]) / 16384.f;
    }
}

// ======================= launch =======================
extern "C" void kernel_launch(void* const* d_in, const int* in_sizes, int n_in,
                              void* d_out, int out_size){
    const float* z1 = (const float*)d_in[0];
    const float* z2 = (const float*)d_in[1];
    const float* W  = (const float*)d_in[2];
    float* out = (float*)d_out;

    cudaFuncSetAttribute(k_mma_gemm, cudaFuncAttributeMaxDynamicSharedMemorySize, G_SMEM);

    k_zero_main<<<1024,256>>>();
    k_wsplit<<<2048,512>>>(W);

    for (int view=0; view<2; view++){
        const float* z = view ? z2 : z1;
        k_rownorm<<<Bn,128>>>(z, view);
        k_ztrans<<<dim3(16,512),dim3(32,8)>>>(z, view);
    }

    // logits GEMMs: [16384 x 2048] = zn @ W^T  (K=512, 3-term split)
    k_mma_gemm<<<dim3(8,128,1),256,G_SMEM>>>(0);
    k_mma_gemm<<<dim3(8,128,1),256,G_SMEM>>>(1);
    // covariance GEMMs: [512 x 512] = z^T z, split-K=32 chunks of 512
    k_mma_gemm<<<dim3(2,4,32),256,G_SMEM>>>(2);
    k_mma_gemm<<<dim3(2,4,32),256,G_SMEM>>>(3);

    k_covfin<<<dim3(512,2),512>>>();

    k_rowstats<<<Bn,256>>>(0);
    k_rowstats<<<Bn,256>>>(1);

    for (int iter=0; iter<3; iter++){
        k_colpass<<<dim3(8,128),256>>>(0, iter);
        k_colpass<<<dim3(8,128),256>>>(1, iter);
        k_u<<<16,256>>>(iter);
        k_rowpass<<<Bn,256>>>(0);
        k_rowpass<<<Bn,256>>>(1);
    }

    k_final<<<1024,256>>>();
    k_finalize<<<1,256>>>(out);
}